// round 17
// baseline (speedup 1.0000x reference)
#include <cuda_runtime.h>
#include <cuda.h>
#include <cuda_fp16.h>
#include <cstdint>
#include <math.h>

#define BB 8
#define NN 89
#define CC 1024
#define HH 512
#define TRI (NN*(NN+1)/2)        // 4005 pairs (j<=i)
#define M_SYM (BB*TRI)           // 32040 unique edge rows
#define MR (BB*NN)               // 712

// Scratch
__device__ __half g_p [(size_t)M_SYM * CC];
__device__ __half g_h1[(size_t)M_SYM * CC];
__device__ float  g_spart[(size_t)8 * M_SYM];
__device__ __half g_wt1[CC*CC];
__device__ __half g_wt2[HH*CC];
__device__ __half g_wadd1[CC*CC];
__device__ __half g_wadd2[CC*CC];
__device__ __half g_wmod1[CC*CC];
__device__ __half g_wmod2[CC*CC];
__device__ __half g_at[MR*CC];
__device__ __half g_mt[MR*CC];
__device__ __half g_t1a[MR*CC];
__device__ __half g_t1m[MR*CC];
__device__ float  g_t2a[MR*CC];
__device__ float  g_t2m[MR*CC];

// ---------------------------------------------------------------------------
__device__ __forceinline__ uint32_t smem_u32(const void* p){
    uint32_t a;
    asm("{ .reg .u64 t; cvta.to.shared.u64 t, %1; cvt.u32.u64 %0, t; }" : "=r"(a) : "l"(p));
    return a;
}
__device__ __forceinline__ void hmma(float c[4], const uint32_t a[4], const uint32_t b[2]){
    asm volatile("mma.sync.aligned.m16n8k16.row.col.f32.f16.f16.f32 "
        "{%0,%1,%2,%3}, {%4,%5,%6,%7}, {%8,%9}, {%0,%1,%2,%3};"
        : "+f"(c[0]), "+f"(c[1]), "+f"(c[2]), "+f"(c[3])
        : "r"(a[0]), "r"(a[1]), "r"(a[2]), "r"(a[3]), "r"(b[0]), "r"(b[1]));
}
__device__ __forceinline__ void ldmx4(uint32_t a[4], uint32_t addr){
    asm volatile("ldmatrix.sync.aligned.m8n8.x4.shared.b16 {%0,%1,%2,%3}, [%4];"
        : "=r"(a[0]), "=r"(a[1]), "=r"(a[2]), "=r"(a[3]) : "r"(addr));
}
__device__ __forceinline__ uint32_t pack_half2(float a, float b){
    __half2 h = __floats2half2_rn(a, b);
    return *reinterpret_cast<uint32_t*>(&h);
}
__device__ __forceinline__ uint32_t sw128(uint32_t b){ return b ^ ((b >> 3) & 0x70u); }

__device__ __forceinline__ void mbar_init(uint32_t a, uint32_t c){
    asm volatile("mbarrier.init.shared.b64 [%0], %1;" :: "r"(a), "r"(c) : "memory");
}
__device__ __forceinline__ void mbar_expect(uint32_t a, uint32_t bytes){
    asm volatile("mbarrier.arrive.expect_tx.shared.b64 _, [%0], %1;" :: "r"(a), "r"(bytes) : "memory");
}
__device__ __forceinline__ void mbar_arrive(uint32_t a){
    asm volatile("mbarrier.arrive.release.cta.shared::cta.b64 _, [%0];" :: "r"(a) : "memory");
}
__device__ __forceinline__ void mbar_wait(uint32_t a, uint32_t par){
    asm volatile("{\n\t.reg .pred P;\n"
        "LW_%=:\n\t"
        "mbarrier.try_wait.parity.acquire.cta.shared::cta.b64 P, [%0], %1, 0x989680;\n\t"
        "@!P bra LW_%=;\n\t}" :: "r"(a), "r"(par) : "memory");
}
__device__ __forceinline__ void tma2d(uint32_t dst, const CUtensorMap* m, int cx, int cy, uint32_t mb){
    asm volatile("cp.async.bulk.tensor.2d.shared::cta.global.tile.mbarrier::complete_tx::bytes "
                 "[%0], [%1, {%2, %3}], [%4];"
                 :: "r"(dst), "l"(m), "r"(cx), "r"(cy), "r"(mb) : "memory");
}
__device__ __forceinline__ void tri_decode(int p, int& j, int& i){
    i = (int)((sqrtf(8.0f*p + 1.0f) - 1.0f) * 0.5f);
    while ((i+1)*(i+2)/2 <= p) i++;
    while (i*(i+1)/2 > p) i--;
    j = p - i*(i+1)/2;
}

// ---------------------------------------------------------------------------
__global__ void __launch_bounds__(256) prod_kernel(const float* __restrict__ x, __half* __restrict__ p){
    const int row = blockIdx.x, seg = threadIdx.x;
    int b = row / TRI, pr = row - b*TRI;
    int j, i; tri_decode(pr, j, i);
    const float4 vj = ((const float4*)(x + (size_t)(b*NN + j)*CC))[seg];
    const float4 vi = ((const float4*)(x + (size_t)(b*NN + i)*CC))[seg];
    uint2 pk = make_uint2(pack_half2(vj.x*vi.x, vj.y*vi.y),
                          pack_half2(vj.z*vi.z, vj.w*vi.w));
    ((uint2*)p)[(size_t)row * 256 + seg] = pk;
}

// z-merged transpose: z=0..4 are CxC weights, z=5 is Wa2 (1024x512)
__global__ void transpose_all(const float* __restrict__ W0, const float* __restrict__ W1,
                              const float* __restrict__ W2, const float* __restrict__ W3,
                              const float* __restrict__ W4, const float* __restrict__ W5,
                              __half* __restrict__ T0, __half* __restrict__ T1,
                              __half* __restrict__ T2, __half* __restrict__ T3,
                              __half* __restrict__ T4, __half* __restrict__ T5)
{
    const float* W; __half* T; int N = CC;
    switch (blockIdx.z){
        case 0: W = W0; T = T0; break;
        case 1: W = W1; T = T1; break;
        case 2: W = W2; T = T2; break;
        case 3: W = W3; T = T3; break;
        case 4: W = W4; T = T4; break;
        default: W = W5; T = T5; N = HH; break;
    }
    int k0 = blockIdx.x*32, n0 = blockIdx.y*32;
    if (n0 >= N) return;
    __shared__ float tile[32][33];
    int tx = threadIdx.x, ty = threadIdx.y;
    #pragma unroll
    for (int r = 0; r < 32; r += 8)
        tile[ty + r][tx] = W[(size_t)(k0 + ty + r)*N + n0 + tx];
    __syncthreads();
    #pragma unroll
    for (int r = 0; r < 32; r += 8)
        T[(size_t)(n0 + ty + r)*CC + k0 + tx] = __float2half(tile[tx][ty + r]);
}

// ---------------------------------------------------------------------------
// FP16 HMMA GEMM: CTA 128x256, BK=64 (128B swizzled rows), TMA staging,
// 4-stage full/empty mbarrier pipeline, WARP-SPECIALIZED producer (warp 8).
// Warps 0-7: compute (warp tile 64x64). Warp 8 lane 0: all TMA issue.
// blockIdx.z selects (mapA,mapB,bias,Cout) pair -> two GEMMs per launch.
//   MODE 1: C half = relu(acc+bias)
//   MODE 2: spart[col][r] = dot(relu(acc+bias), wvec)
//   MODE 4: C fp32 = acc+bias (no relu)
// ---------------------------------------------------------------------------
#define BK 64
#define STAGES 4
#define A_ST_B 16384
#define B_ST_B 32768
#define STAGE_B (A_ST_B + B_ST_B)

template<int MODE>
__global__ void __launch_bounds__(288, 1) hgemm(
    const __grid_constant__ CUtensorMap mA0, const __grid_constant__ CUtensorMap mB0,
    const __grid_constant__ CUtensorMap mA1, const __grid_constant__ CUtensorMap mB1,
    const float* __restrict__ bias0, const float* __restrict__ bias1,
    void* __restrict__ C0, void* __restrict__ C1,
    const float* __restrict__ wvec, float* __restrict__ spart,
    int M, int K, int N)
{
    extern __shared__ __align__(1024) char sh[];
    __shared__ __align__(8) unsigned long long mbar[2*STAGES];   // full[4] + empty[4]

    const CUtensorMap* mapA = blockIdx.z ? &mA1 : &mA0;
    const CUtensorMap* mapB = blockIdx.z ? &mB1 : &mB0;
    const float* bias = blockIdx.z ? bias1 : bias0;
    void* Cout        = blockIdx.z ? C1 : C0;

    const int t = threadIdx.x, warp = t >> 5, lane = t & 31;
    const int g = lane >> 2, tig = lane & 3;
    const int mBase = blockIdx.y * 128, nBase = blockIdx.x * 256;

    const uint32_t uS  = smem_u32(sh);
    const uint32_t uMF = smem_u32(&mbar[0]);         // full barriers
    const uint32_t uME = smem_u32(&mbar[STAGES]);    // empty barriers

    if (t == 0){
        #pragma unroll
        for (int s = 0; s < STAGES; s++){
            mbar_init(uMF + s*8, 1);    // TMA complete_tx
            mbar_init(uME + s*8, 8);    // one arrive per compute warp
        }
        asm volatile("fence.proxy.async.shared::cta;" ::: "memory");
    }
    __syncthreads();

    const int KT = K / BK;

    if (warp == 8){
        // ---------------- producer warp ----------------
        if (lane == 0){
            int phE[STAGES] = {0, 0, 0, 0};
            for (int kt = 0; kt < KT; kt++){
                const int b = kt % STAGES;
                if (kt >= STAGES){ mbar_wait(uME + b*8, phE[b]); phE[b] ^= 1; }
                mbar_expect(uMF + b*8, STAGE_B);
                tma2d(uS + b*STAGE_B,          mapA, kt*BK, mBase, uMF + b*8);
                tma2d(uS + b*STAGE_B + A_ST_B, mapB, kt*BK, nBase, uMF + b*8);
            }
        }
    } else {
        // ---------------- compute warps ----------------
        const int wm = (warp >> 2) * 64, wn = (warp & 3) * 64;
        const int laneR = lane & 15, laneK = (lane >> 4) << 3;
        const int bg4 = lane >> 3, br = lane & 7;

        float acc[4][8][4];
        #pragma unroll
        for (int mi = 0; mi < 4; mi++)
            #pragma unroll
            for (int ni = 0; ni < 8; ni++)
                #pragma unroll
                for (int q = 0; q < 4; q++) acc[mi][ni][q] = 0.f;

        int phF[STAGES] = {0, 0, 0, 0};
        for (int kt = 0; kt < KT; kt++){
            const int b = kt % STAGES;
            mbar_wait(uMF + b*8, phF[b]); phF[b] ^= 1;

            const uint32_t uA = uS + (uint32_t)(b * STAGE_B);
            const uint32_t uB = uA + A_ST_B;

            #pragma unroll
            for (int ko16 = 0; ko16 < 4; ko16++){
                const int ko = ko16 * 16;
                uint32_t af[4][4], bf[8][2];
                #pragma unroll
                for (int mi = 0; mi < 4; mi++){
                    uint32_t byte = (uint32_t)((wm + mi*16 + laneR)*128 + (ko + laneK)*2);
                    ldmx4(af[mi], uA + sw128(byte));
                }
                #pragma unroll
                for (int nq = 0; nq < 4; nq++){
                    uint32_t r4[4];
                    int n = wn + nq*16 + (bg4 >> 1)*8 + br;
                    int k = ko + (bg4 & 1)*8;
                    uint32_t byte = (uint32_t)(n*128 + k*2);
                    ldmx4(r4, uB + sw128(byte));
                    bf[nq*2  ][0] = r4[0]; bf[nq*2  ][1] = r4[1];
                    bf[nq*2+1][0] = r4[2]; bf[nq*2+1][1] = r4[3];
                }
                // early release after last fragment loads of this stage
                if (ko16 == 3 && lane == 0) mbar_arrive(uME + b*8);
                #pragma unroll
                for (int mi = 0; mi < 4; mi++)
                    #pragma unroll
                    for (int ni = 0; ni < 8; ni++)
                        hmma(acc[mi][ni], af[mi], bf[ni]);
            }
        }

        // ---------------- epilogue ----------------
        if (MODE == 1 || MODE == 4){
            #pragma unroll
            for (int mi = 0; mi < 4; mi++)
                #pragma unroll
                for (int ni = 0; ni < 8; ni++){
                    const int cb = nBase + wn + ni*8 + 2*tig;
                    const float2 bs = *(const float2*)(bias + cb);
                    #pragma unroll
                    for (int hh = 0; hh < 2; hh++){
                        const int r = mBase + wm + mi*16 + g + hh*8;
                        if (r >= M) continue;
                        float z0 = acc[mi][ni][hh*2+0] + bs.x;
                        float z1 = acc[mi][ni][hh*2+1] + bs.y;
                        if (MODE == 1){
                            z0 = fmaxf(z0, 0.f); z1 = fmaxf(z1, 0.f);
                            *(uint32_t*)((__half*)Cout + (size_t)r * N + cb) = pack_half2(z0, z1);
                        } else {
                            *(float2*)((float*)Cout + (size_t)r * N + cb) = make_float2(z0, z1);
                        }
                    }
                }
        } else {
            float rs[4][2];
            #pragma unroll
            for (int mi = 0; mi < 4; mi++){ rs[mi][0] = 0.f; rs[mi][1] = 0.f; }
            #pragma unroll
            for (int mi = 0; mi < 4; mi++)
                #pragma unroll
                for (int ni = 0; ni < 8; ni++){
                    const int cb = nBase + wn + ni*8 + 2*tig;
                    const float2 bs = *(const float2*)(bias + cb);
                    const float2 wv = *(const float2*)(wvec + cb);
                    #pragma unroll
                    for (int hh = 0; hh < 2; hh++){
                        float z0 = fmaxf(acc[mi][ni][hh*2+0] + bs.x, 0.f);
                        float z1 = fmaxf(acc[mi][ni][hh*2+1] + bs.y, 0.f);
                        rs[mi][hh] += z0*wv.x + z1*wv.y;
                    }
                }
            const int col = blockIdx.x * 4 + (warp & 3);
            #pragma unroll
            for (int mi = 0; mi < 4; mi++)
                #pragma unroll
                for (int hh = 0; hh < 2; hh++){
                    float v = rs[mi][hh];
                    v += __shfl_xor_sync(0xffffffffu, v, 1);
                    v += __shfl_xor_sync(0xffffffffu, v, 2);
                    const int r = mBase + wm + mi*16 + g + hh*8;
                    if (tig == 0 && r < M)
                        spart[(size_t)col * M_SYM + r] = v;
                }
        }
    }
}

// ---------------------------------------------------------------------------
__global__ void __launch_bounds__(256) combine_kernel(
    const float* __restrict__ x, const float* __restrict__ t2a,
    const float* __restrict__ t2m, float* __restrict__ out)
{
    size_t idx = (size_t)blockIdx.x * 256 + threadIdx.x;
    float4 xv = ((const float4*)x)[idx];
    float4 av = ((const float4*)t2a)[idx];
    float4 mv = ((const float4*)t2m)[idx];
    const float k = 1.f/3.f;
    ((float4*)out)[idx] = make_float4((xv.x+av.x+mv.x)*k, (xv.y+av.y+mv.y)*k,
                                      (xv.z+av.z+mv.z)*k, (xv.w+av.w+mv.w)*k);
}

// ---------------------------------------------------------------------------
__global__ void __launch_bounds__(256) agg_kernel(
    const float* __restrict__ x, const float* __restrict__ spart,
    const float* __restrict__ ba3,
    const float* __restrict__ adj_add, const float* __restrict__ adj_mod,
    __half* __restrict__ at, __half* __restrict__ mt)
{
    __shared__ float sv_sh[NN];
    int bi = blockIdx.x;
    int b = bi / NN, i = bi - b*NN;
    if (threadIdx.x < NN){
        int j = threadIdx.x;
        int lo = j <= i ? j : i;
        int hi = j <= i ? i : j;
        int row = b*TRI + hi*(hi+1)/2 + lo;
        float v = ba3[0];
        #pragma unroll
        for (int c = 0; c < 8; c++) v += spart[(size_t)c * M_SYM + row];
        sv_sh[j] = 1.f / (1.f + expf(-v));
    }
    __syncthreads();

    int f = threadIdx.x * 4;
    float4 aa = make_float4(0,0,0,0), mm = make_float4(0,0,0,0);
    for (int j = 0; j < NN; j++){
        float wa = sv_sh[j] * adj_add[j*NN + i];
        float wm = adj_mod[j*NN + i];
        float4 xv = *(const float4*)(x + (size_t)(b*NN + j)*CC + f);
        aa.x = fmaf(wa, xv.x, aa.x); aa.y = fmaf(wa, xv.y, aa.y);
        aa.z = fmaf(wa, xv.z, aa.z); aa.w = fmaf(wa, xv.w, aa.w);
        mm.x = fmaf(wm, xv.x, mm.x); mm.y = fmaf(wm, xv.y, mm.y);
        mm.z = fmaf(wm, xv.z, mm.z); mm.w = fmaf(wm, xv.w, mm.w);
    }
    float4 xv = *(const float4*)(x + (size_t)bi * CC + f);
    mm.x *= xv.x; mm.y *= xv.y; mm.z *= xv.z; mm.w *= xv.w;
    ((uint2*)(at + (size_t)bi * CC))[threadIdx.x] =
        make_uint2(pack_half2(aa.x, aa.y), pack_half2(aa.z, aa.w));
    ((uint2*)(mt + (size_t)bi * CC))[threadIdx.x] =
        make_uint2(pack_half2(mm.x, mm.y), pack_half2(mm.z, mm.w));
}

// ---------------------------------------------------------------------------
typedef CUresult (*EncodeFn)(CUtensorMap*, CUtensorMapDataType, cuuint32_t, void*,
    const cuuint64_t*, const cuuint64_t*, const cuuint32_t*, const cuuint32_t*,
    CUtensorMapInterleave, CUtensorMapSwizzle, CUtensorMapL2promotion, CUtensorMapFloatOOBfill);

static EncodeFn get_encoder(){
    static EncodeFn fn = nullptr;
    if (!fn){
        cudaDriverEntryPointQueryResult qr;
#if CUDART_VERSION >= 12050
        cudaGetDriverEntryPointByVersion("cuTensorMapEncodeTiled", (void**)&fn, 12000,
                                         cudaEnableDefault, &qr);
#else
        cudaGetDriverEntryPoint("cuTensorMapEncodeTiled", (void**)&fn, cudaEnableDefault, &qr);
#endif
    }
    return fn;
}
static void make_map(CUtensorMap* m, void* ptr, uint64_t kdim, uint64_t rows, uint32_t boxRows){
    cuuint64_t dims[2] = {kdim, rows};
    cuuint64_t strides[1] = {kdim * 2};
    cuuint32_t box[2] = {BK, boxRows};
    cuuint32_t es[2] = {1, 1};
    get_encoder()(m, CU_TENSOR_MAP_DATA_TYPE_FLOAT16, 2, ptr, dims, strides, box, es,
        CU_TENSOR_MAP_INTERLEAVE_NONE, CU_TENSOR_MAP_SWIZZLE_128B,
        CU_TENSOR_MAP_L2_PROMOTION_L2_128B, CU_TENSOR_MAP_FLOAT_OOB_FILL_NONE);
}

extern "C" void kernel_launch(void* const* d_in, const int* in_sizes, int n_in,
                              void* d_out, int out_size)
{
    const float* x    = (const float*)d_in[0];
    const float* Wa1  = (const float*)d_in[3];
    const float* ba1  = (const float*)d_in[4];
    const float* Wa2  = (const float*)d_in[5];
    const float* ba2  = (const float*)d_in[6];
    const float* Wa3  = (const float*)d_in[7];
    const float* ba3  = (const float*)d_in[8];
    const float* Wadd1 = (const float*)d_in[9];
    const float* badd1 = (const float*)d_in[10];
    const float* Wadd2 = (const float*)d_in[11];
    const float* badd2 = (const float*)d_in[12];
    const float* Wmod1 = (const float*)d_in[13];
    const float* bmod1 = (const float*)d_in[14];
    const float* Wmod2 = (const float*)d_in[15];
    const float* bmod2 = (const float*)d_in[16];
    float* out = (float*)d_out;

    __half *p, *h1, *wt1, *wt2, *wadd1, *wadd2, *wmod1, *wmod2, *at, *mt, *t1a, *t1m;
    float *spart, *t2a, *t2m;
    cudaGetSymbolAddress((void**)&p,    g_p);
    cudaGetSymbolAddress((void**)&h1,   g_h1);
    cudaGetSymbolAddress((void**)&spart,g_spart);
    cudaGetSymbolAddress((void**)&wt1,  g_wt1);
    cudaGetSymbolAddress((void**)&wt2,  g_wt2);
    cudaGetSymbolAddress((void**)&wadd1,g_wadd1);
    cudaGetSymbolAddress((void**)&wadd2,g_wadd2);
    cudaGetSymbolAddress((void**)&wmod1,g_wmod1);
    cudaGetSymbolAddress((void**)&wmod2,g_wmod2);
    cudaGetSymbolAddress((void**)&at,   g_at);
    cudaGetSymbolAddress((void**)&mt,   g_mt);
    cudaGetSymbolAddress((void**)&t1a,  g_t1a);
    cudaGetSymbolAddress((void**)&t1m,  g_t1m);
    cudaGetSymbolAddress((void**)&t2a,  g_t2a);
    cudaGetSymbolAddress((void**)&t2m,  g_t2m);

    const int M = M_SYM;
    const int MT = (M + 127) / 128;          // 251
    const int MRT = (MR + 127) / 128;        // 6
    const int SMEM = STAGES * STAGE_B;       // 196608 B

    cudaFuncSetAttribute(hgemm<1>, cudaFuncAttributeMaxDynamicSharedMemorySize, SMEM);
    cudaFuncSetAttribute(hgemm<2>, cudaFuncAttributeMaxDynamicSharedMemorySize, SMEM);
    cudaFuncSetAttribute(hgemm<4>, cudaFuncAttributeMaxDynamicSharedMemorySize, SMEM);

    CUtensorMap mA1, mB1, mA2, mB2, mAT, mMT, mBadd1, mBmod1, mT1A, mT1M, mBadd2, mBmod2;
    make_map(&mA1, p,   CC, M,  128);
    make_map(&mB1, wt1, CC, CC, 256);
    make_map(&mA2, h1,  CC, M,  128);
    make_map(&mB2, wt2, CC, HH, 256);
    make_map(&mAT,   at,    CC, MR, 128);
    make_map(&mMT,   mt,    CC, MR, 128);
    make_map(&mBadd1,wadd1, CC, CC, 256);
    make_map(&mBmod1,wmod1, CC, CC, 256);
    make_map(&mT1A,  t1a,   CC, MR, 128);
    make_map(&mT1M,  t1m,   CC, MR, 128);
    make_map(&mBadd2,wadd2, CC, CC, 256);
    make_map(&mBmod2,wmod2, CC, CC, 256);

    // prep: all six transposes in one launch + edge products
    transpose_all<<<dim3(32, 32, 6), dim3(32,8)>>>(
        Wa1, Wadd1, Wmod1, Wadd2, Wmod2, Wa2,
        wt1, wadd1, wmod1, wadd2, wmod2, wt2);
    prod_kernel<<<M, 256>>>(x, p);

    // h1 = relu(p @ Wa1 + ba1)   [half out]
    hgemm<1><<<dim3(CC/256, MT, 1), 288, SMEM>>>(
        mA1, mB1, mA1, mB1, ba1, ba1, h1, h1, nullptr, nullptr, M, CC, CC);
    // s partials
    hgemm<2><<<dim3(HH/256, MT, 1), 288, SMEM>>>(
        mA2, mB2, mA2, mB2, ba2, ba2, nullptr, nullptr, Wa3, spart, M, CC, HH);

    agg_kernel<<<MR, 256>>>(x, spart, ba3, (const float*)d_in[1], (const float*)d_in[2], at, mt);

    // layer-1 pair (relu, half out)
    hgemm<1><<<dim3(CC/256, MRT, 2), 288, SMEM>>>(
        mAT, mBadd1, mMT, mBmod1, badd1, bmod1, t1a, t1m, nullptr, nullptr, MR, CC, CC);
    // layer-2 pair (no relu, fp32 out)
    hgemm<4><<<dim3(CC/256, MRT, 2), 288, SMEM>>>(
        mT1A, mBadd2, mT1M, mBmod2, badd2, bmod2, t2a, t2m, nullptr, nullptr, MR, CC, CC);

    combine_kernel<<<(MR*CC/4 + 255)/256, 256>>>(x, t2a, t2m, out);
}